// round 1
// baseline (speedup 1.0000x reference)
#include <cuda_runtime.h>
#include <cstdint>

// Problem constants
#define Bv 8
#define Tv 1024
#define Cv 768
#define Hv 12
#define HDv 64
#define Mv (Bv*Tv)          // 8192 rows
#define NQKV (3*Cv)         // 2304

#define NEG_INF __int_as_float(0xff800000u)

// Scratch (allocation-free rule: __device__ globals)
__device__ __align__(16) float g_Q[Bv*Hv*Tv*HDv];   // [B,H,T,64]
__device__ __align__(16) float g_K[Bv*Hv*Tv*HDv];
__device__ __align__(16) float g_V[Bv*Hv*Tv*HDv];
__device__ __align__(16) float g_O[Mv*Cv];          // [B*T, C] attention output

// ---------------------------------------------------------------------------
// Generic 128x128x16 fp32 GEMM, 256 threads, 8x8 per-thread tile.
// QKV=true : A = x [8192,768], B = W_qkv [768,2304]; epilogue scatters to
//            g_Q/g_K/g_V in [B,H,T,64] layout (+bias).
// QKV=false: A = g_O [8192,768], B = W_proj [768,768]; epilogue writes
//            Cout (+bias).
// ---------------------------------------------------------------------------
template<int N, bool QKV>
__global__ void __launch_bounds__(256) gemm_kernel(const float* __restrict__ A_in,
                                                   const float* __restrict__ Bm,
                                                   const float* __restrict__ bias,
                                                   float* __restrict__ Cout)
{
    __shared__ float As[16][128];   // [k][m] transposed
    __shared__ float Bs[16][128];   // [k][n]

    const float* A = QKV ? A_in : (const float*)g_O;

    const int bm = blockIdx.y * 128;
    const int bn = blockIdx.x * 128;
    const int tid = threadIdx.x;
    const int tx = tid & 15;
    const int ty = tid >> 4;

    float acc[8][8];
    #pragma unroll
    for (int i = 0; i < 8; i++)
        #pragma unroll
        for (int j = 0; j < 8; j++) acc[i][j] = 0.f;

    for (int k0 = 0; k0 < Cv; k0 += 16) {
        // A tile: 128 rows x 16 k, load float4, store transposed
        #pragma unroll
        for (int u = 0; u < 2; u++) {
            int f = tid + u * 256;           // 0..511 float4 slots
            int row = f >> 2;                // 0..127
            int kq  = (f & 3) << 2;          // 0,4,8,12
            float4 v = *(const float4*)(A + (size_t)(bm + row) * Cv + k0 + kq);
            As[kq + 0][row] = v.x;
            As[kq + 1][row] = v.y;
            As[kq + 2][row] = v.z;
            As[kq + 3][row] = v.w;
        }
        // B tile: 16 k x 128 n
        #pragma unroll
        for (int u = 0; u < 2; u++) {
            int f = tid + u * 256;
            int row = f >> 5;                // 0..15
            int c4  = (f & 31) << 2;         // 0..124
            *(float4*)(&Bs[row][c4]) =
                *(const float4*)(Bm + (size_t)(k0 + row) * N + bn + c4);
        }
        __syncthreads();

        #pragma unroll
        for (int k = 0; k < 16; k++) {
            float ra[8], rb[8];
            *(float4*)(ra)     = *(const float4*)&As[k][ty * 8];
            *(float4*)(ra + 4) = *(const float4*)&As[k][ty * 8 + 4];
            *(float4*)(rb)     = *(const float4*)&Bs[k][tx * 8];
            *(float4*)(rb + 4) = *(const float4*)&Bs[k][tx * 8 + 4];
            #pragma unroll
            for (int i = 0; i < 8; i++)
                #pragma unroll
                for (int j = 0; j < 8; j++)
                    acc[i][j] = fmaf(ra[i], rb[j], acc[i][j]);
        }
        __syncthreads();
    }

    // Epilogue
    #pragma unroll
    for (int i = 0; i < 8; i++) {
        int row = bm + ty * 8 + i;          // global m (= b*T + t)
        int b = row >> 10;
        int t = row & 1023;
        #pragma unroll
        for (int j = 0; j < 8; j++) {
            int col = bn + tx * 8 + j;
            float v = acc[i][j] + bias[col];
            if (QKV) {
                int grp = col / Cv;          // 0=Q, 1=K, 2=V
                int cc  = col - grp * Cv;
                int h   = cc >> 6;
                int d   = cc & 63;
                float* dst = (grp == 0) ? g_Q : ((grp == 1) ? g_K : g_V);
                dst[(((size_t)b * Hv + h) * Tv + t) * 64 + d] = v;
            } else {
                Cout[(size_t)row * Cv + col] = v;
            }
        }
    }
}

// ---------------------------------------------------------------------------
// Flash attention: one CTA per (b, h, q-tile of 64 rows). 256 threads = 16x16,
// each thread owns a 4x4 output tile. Causal: only k-tiles kt <= qt.
// Smem: Qs natural [r][d], KVs XOR-swizzled (d ^ (c&60)) so scalar column
// reads are <=2-way conflicted at stride 64, Ps natural. Total = 48 KB.
// ---------------------------------------------------------------------------
__global__ void __launch_bounds__(256) attn_kernel()
{
    __shared__ float Qs[64 * 64];
    __shared__ float KVs[64 * 64];
    __shared__ float Ps[64 * 64];

    const int qt = blockIdx.x;   // 0..15
    const int h  = blockIdx.y;   // 0..11
    const int b  = blockIdx.z;   // 0..7
    const int tid = threadIdx.x;
    const int tx = tid & 15;
    const int ty = tid >> 4;

    const size_t base = ((size_t)b * Hv + h) * Tv * HDv;
    const float* Qg = g_Q + base + (size_t)qt * 64 * 64;
    const float* Kg = g_K + base;
    const float* Vg = g_V + base;

    // Load Q tile (natural layout)
    #pragma unroll
    for (int u = 0; u < 4; u++) {
        int f = tid + u * 256;
        int r  = f >> 4;
        int d4 = (f & 15) << 2;
        *(float4*)&Qs[r * 64 + d4] = *(const float4*)(Qg + r * 64 + d4);
    }

    float o[4][4];
    float mrow[4], lrow[4];
    #pragma unroll
    for (int i = 0; i < 4; i++) {
        mrow[i] = NEG_INF;
        lrow[i] = 0.f;
        #pragma unroll
        for (int j = 0; j < 4; j++) o[i][j] = 0.f;
    }

    const float scale = 0.125f;   // 1/sqrt(64)

    for (int kt = 0; kt <= qt; kt++) {
        __syncthreads();   // Q visible (1st iter); prev-iter V reads done

        // Load K tile, swizzled
        #pragma unroll
        for (int u = 0; u < 4; u++) {
            int f = tid + u * 256;
            int c  = f >> 4;
            int d4 = (f & 15) << 2;
            *(float4*)&KVs[c * 64 + (d4 ^ (c & 60))] =
                *(const float4*)(Kg + (size_t)(kt * 64 + c) * 64 + d4);
        }
        __syncthreads();

        // S = Q @ K^T
        float s[4][4];
        #pragma unroll
        for (int i = 0; i < 4; i++)
            #pragma unroll
            for (int j = 0; j < 4; j++) s[i][j] = 0.f;

        #pragma unroll 8
        for (int d = 0; d < 64; d++) {
            float qa[4], kb[4];
            #pragma unroll
            for (int i = 0; i < 4; i++) qa[i] = Qs[(ty * 4 + i) * 64 + d];
            #pragma unroll
            for (int j = 0; j < 4; j++) {
                int c = tx * 4 + j;
                kb[j] = KVs[c * 64 + (d ^ (c & 60))];
            }
            #pragma unroll
            for (int i = 0; i < 4; i++)
                #pragma unroll
                for (int j = 0; j < 4; j++)
                    s[i][j] = fmaf(qa[i], kb[j], s[i][j]);
        }

        // Scale + causal mask + online softmax (row stats across 16 lanes)
        float pnew[4][4];
        #pragma unroll
        for (int i = 0; i < 4; i++) {
            float mx = NEG_INF;
            #pragma unroll
            for (int j = 0; j < 4; j++) {
                float v = s[i][j] * scale;
                if (kt == qt && (tx * 4 + j) > (ty * 4 + i)) v = NEG_INF;
                s[i][j] = v;
                mx = fmaxf(mx, v);
            }
            #pragma unroll
            for (int off = 8; off >= 1; off >>= 1)
                mx = fmaxf(mx, __shfl_xor_sync(0xffffffffu, mx, off));
            float mnew = fmaxf(mrow[i], mx);
            float corr = __expf(mrow[i] - mnew);   // exp(-inf)=0 on first tile
            float rs = 0.f;
            #pragma unroll
            for (int j = 0; j < 4; j++) {
                float p = __expf(s[i][j] - mnew);  // masked -> exp(-inf)=0
                pnew[i][j] = p;
                rs += p;
            }
            #pragma unroll
            for (int off = 8; off >= 1; off >>= 1)
                rs += __shfl_xor_sync(0xffffffffu, rs, off);
            lrow[i] = lrow[i] * corr + rs;
            mrow[i] = mnew;
            #pragma unroll
            for (int j = 0; j < 4; j++) o[i][j] *= corr;
        }

        // Store P
        #pragma unroll
        for (int i = 0; i < 4; i++)
            #pragma unroll
            for (int j = 0; j < 4; j++)
                Ps[(ty * 4 + i) * 64 + tx * 4 + j] = pnew[i][j];
        __syncthreads();   // all K reads done + P visible before V overwrite

        // Load V tile over K buffer, swizzled
        #pragma unroll
        for (int u = 0; u < 4; u++) {
            int f = tid + u * 256;
            int c  = f >> 4;
            int d4 = (f & 15) << 2;
            *(float4*)&KVs[c * 64 + (d4 ^ (c & 60))] =
                *(const float4*)(Vg + (size_t)(kt * 64 + c) * 64 + d4);
        }
        __syncthreads();

        // O += P @ V
        #pragma unroll 8
        for (int c = 0; c < 64; c++) {
            float pa[4], vb[4];
            #pragma unroll
            for (int i = 0; i < 4; i++) pa[i] = Ps[(ty * 4 + i) * 64 + c];
            #pragma unroll
            for (int j = 0; j < 4; j++) {
                int d = tx * 4 + j;
                vb[j] = KVs[c * 64 + (d ^ (c & 60))];
            }
            #pragma unroll
            for (int i = 0; i < 4; i++)
                #pragma unroll
                for (int j = 0; j < 4; j++)
                    o[i][j] = fmaf(pa[i], vb[j], o[i][j]);
        }
    }

    // Epilogue: normalize and write O in [B*T, C] layout (col = h*64 + d)
    #pragma unroll
    for (int i = 0; i < 4; i++) {
        float inv = 1.0f / lrow[i];
        int t = qt * 64 + ty * 4 + i;
        #pragma unroll
        for (int j = 0; j < 4; j++) {
            g_O[((size_t)b * Tv + t) * Cv + h * 64 + tx * 4 + j] = o[i][j] * inv;
        }
    }
}

// ---------------------------------------------------------------------------
// Launch: QKV GEMM -> flash attention -> out-proj GEMM (all default stream,
// graph-capturable, allocation-free).
// Inputs (metadata order): x, mask(unused - causal is recomputed), W_qkv,
// b_qkv, W_proj, b_proj.
// ---------------------------------------------------------------------------
extern "C" void kernel_launch(void* const* d_in, const int* in_sizes, int n_in,
                              void* d_out, int out_size)
{
    const float* x      = (const float*)d_in[0];
    const float* W_qkv  = (const float*)d_in[2];
    const float* b_qkv  = (const float*)d_in[3];
    const float* W_proj = (const float*)d_in[4];
    const float* b_proj = (const float*)d_in[5];
    float* out = (float*)d_out;

    gemm_kernel<NQKV, true><<<dim3(NQKV / 128, Mv / 128), 256>>>(x, W_qkv, b_qkv, nullptr);
    attn_kernel<<<dim3(Tv / 64, Hv, Bv), 256>>>();
    gemm_kernel<Cv, false><<<dim3(Cv / 128, Mv / 128), 256>>>(nullptr, W_proj, b_proj, out);
}

// round 2
// speedup vs baseline: 1.1864x; 1.1864x over previous
#include <cuda_runtime.h>
#include <cstdint>

// Problem constants
#define Bv 8
#define Tv 1024
#define Cv 768
#define Hv 12
#define HDv 64
#define Mv (Bv*Tv)          // 8192 rows
#define NQKV (3*Cv)         // 2304

#define NEG_INF __int_as_float(0xff800000u)

typedef unsigned long long ull;

// f32x2 packed-math helpers (sm_100+ PTX; 2 FMAs per issue slot)
__device__ __forceinline__ ull pack2(float lo, float hi) {
    ull r; asm("mov.b64 %0, {%1, %2};" : "=l"(r) : "f"(lo), "f"(hi)); return r;
}
__device__ __forceinline__ float2 unpack2(ull v) {
    float2 r; asm("mov.b64 {%0, %1}, %2;" : "=f"(r.x), "=f"(r.y) : "l"(v)); return r;
}
__device__ __forceinline__ void fma2(ull& d, ull a, ull b) {
    asm("fma.rn.f32x2 %0, %1, %2, %0;" : "+l"(d) : "l"(a), "l"(b));
}
__device__ __forceinline__ ull mul2(ull a, ull b) {
    ull r; asm("mul.rn.f32x2 %0, %1, %2;" : "=l"(r) : "l"(a), "l"(b)); return r;
}

// Scratch (allocation-free rule: __device__ globals)
__device__ __align__(16) float g_Q[Bv*Hv*Tv*HDv];   // [B,H,T,64]
__device__ __align__(16) float g_K[Bv*Hv*Tv*HDv];
__device__ __align__(16) float g_V[Bv*Hv*Tv*HDv];
__device__ __align__(16) float g_O[Mv*Cv];          // [B*T, C] attention output

// ---------------------------------------------------------------------------
// 128x128x16 fp32 GEMM, 256 threads, 8x8 per-thread tile via f32x2 (acc paired
// along j). Double-buffered smem + register prefetch; 2 CTAs/SM.
// QKV=true : A = x [8192,768], B = W_qkv [768,2304] -> scatter to g_Q/K/V.
// QKV=false: A = g_O [8192,768], B = W_proj [768,768] -> Cout.
// ---------------------------------------------------------------------------
template<int N, bool QKV>
__global__ void __launch_bounds__(256, 2) gemm_kernel(const float* __restrict__ A_in,
                                                      const float* __restrict__ Bm,
                                                      const float* __restrict__ bias,
                                                      float* __restrict__ Cout)
{
    __shared__ float As[2][16][128];   // [buf][k][m]
    __shared__ float Bs[2][16][128];   // [buf][k][n]

    const float* A = QKV ? A_in : (const float*)g_O;

    const int bm = blockIdx.y * 128;
    const int bn = blockIdx.x * 128;
    const int tid = threadIdx.x;
    const int tx = tid & 15;
    const int ty = tid >> 4;

    // Loader geometry: 2 float4 each for A (rows r, r+64) and B (k-rows r, r+8)
    const int arow = tid >> 2;           // 0..63
    const int akq  = (tid & 3) << 2;     // 0,4,8,12
    const int brow = tid >> 5;           // 0..7
    const int bc4  = (tid & 31) << 2;    // 0..124

    const float* Ag  = A + (size_t)(bm + arow) * Cv + akq;
    const float* Ag2 = Ag + (size_t)64 * Cv;
    const float* Bg  = Bm + (size_t)brow * N + bn + bc4;
    const float* Bg2 = Bg + (size_t)8 * N;

    ull acc[8][4];
    #pragma unroll
    for (int i = 0; i < 8; i++)
        #pragma unroll
        for (int jj = 0; jj < 4; jj++) acc[i][jj] = 0ull;  // (0.f,0.f)

    // Preload k-tile 0 into buffer 0
    float4 a0 = *(const float4*)Ag;
    float4 a1 = *(const float4*)Ag2;
    float4 b0 = *(const float4*)Bg;
    float4 b1 = *(const float4*)Bg2;
    As[0][akq+0][arow] = a0.x; As[0][akq+1][arow] = a0.y;
    As[0][akq+2][arow] = a0.z; As[0][akq+3][arow] = a0.w;
    As[0][akq+0][arow+64] = a1.x; As[0][akq+1][arow+64] = a1.y;
    As[0][akq+2][arow+64] = a1.z; As[0][akq+3][arow+64] = a1.w;
    *(float4*)&Bs[0][brow  ][bc4] = b0;
    *(float4*)&Bs[0][brow+8][bc4] = b1;
    __syncthreads();

    const int KT = Cv / 16;   // 48
    for (int kt = 0; kt < KT; kt++) {
        const int buf = kt & 1;
        const bool more = (kt + 1 < KT);
        if (more) {
            const int k0 = (kt + 1) * 16;
            a0 = *(const float4*)(Ag  + k0);
            a1 = *(const float4*)(Ag2 + k0);
            b0 = *(const float4*)(Bg  + (size_t)k0 * N);
            b1 = *(const float4*)(Bg2 + (size_t)k0 * N);
        }

        #pragma unroll
        for (int k = 0; k < 16; k++) {
            float4 ra0 = *(const float4*)&As[buf][k][ty * 8];
            float4 ra1 = *(const float4*)&As[buf][k][ty * 8 + 4];
            double2 rbl = *(const double2*)&Bs[buf][k][tx * 8];
            double2 rbh = *(const double2*)&Bs[buf][k][tx * 8 + 4];
            ull rb[4] = { __double_as_longlong(rbl.x), __double_as_longlong(rbl.y),
                          __double_as_longlong(rbh.x), __double_as_longlong(rbh.y) };
            float ra[8] = { ra0.x, ra0.y, ra0.z, ra0.w, ra1.x, ra1.y, ra1.z, ra1.w };
            #pragma unroll
            for (int i = 0; i < 8; i++) {
                ull a2 = pack2(ra[i], ra[i]);
                #pragma unroll
                for (int jj = 0; jj < 4; jj++) fma2(acc[i][jj], a2, rb[jj]);
            }
        }

        if (more) {
            const int nb = buf ^ 1;
            As[nb][akq+0][arow] = a0.x; As[nb][akq+1][arow] = a0.y;
            As[nb][akq+2][arow] = a0.z; As[nb][akq+3][arow] = a0.w;
            As[nb][akq+0][arow+64] = a1.x; As[nb][akq+1][arow+64] = a1.y;
            As[nb][akq+2][arow+64] = a1.z; As[nb][akq+3][arow+64] = a1.w;
            *(float4*)&Bs[nb][brow  ][bc4] = b0;
            *(float4*)&Bs[nb][brow+8][bc4] = b1;
        }
        __syncthreads();
    }

    // Epilogue: 8 contiguous cols per thread -> 2 float4 stores per row
    const int col0 = bn + tx * 8;
    float4 bv0 = *(const float4*)&bias[col0];
    float4 bv1 = *(const float4*)&bias[col0 + 4];
    #pragma unroll
    for (int i = 0; i < 8; i++) {
        const int row = bm + ty * 8 + i;
        float2 v0 = unpack2(acc[i][0]);
        float2 v1 = unpack2(acc[i][1]);
        float2 v2 = unpack2(acc[i][2]);
        float2 v3 = unpack2(acc[i][3]);
        float4 o0 = make_float4(v0.x + bv0.x, v0.y + bv0.y, v1.x + bv0.z, v1.y + bv0.w);
        float4 o1 = make_float4(v2.x + bv1.x, v2.y + bv1.y, v3.x + bv1.z, v3.y + bv1.w);
        if (QKV) {
            const int b = row >> 10;
            const int t = row & 1023;
            const int grp = col0 / Cv;            // whole 8-col block in one group
            const int cc  = col0 - grp * Cv;
            const int h   = cc >> 6;
            const int d   = cc & 63;              // 8-aligned, doesn't cross 64
            float* dst = (grp == 0) ? g_Q : ((grp == 1) ? g_K : g_V);
            float* p = &dst[(((size_t)b * Hv + h) * Tv + t) * 64 + d];
            *(float4*)p       = o0;
            *(float4*)(p + 4) = o1;
        } else {
            float* p = &Cout[(size_t)row * Cv + col0];
            *(float4*)p       = o0;
            *(float4*)(p + 4) = o1;
        }
    }
}

// ---------------------------------------------------------------------------
// Flash attention: one CTA per (b, h, 64-row q-tile). 256 threads = 16x16,
// 4x4 per-thread output tile. f32x2 math: S=QK^T paired over d (contiguous
// operands, horizontal add at end), O=PV paired over j.
// KVs XOR-swizzled per 4-float chunk: addr = c*64 + ((d&60)^(c&60)) + (d&3).
// ---------------------------------------------------------------------------
__global__ void __launch_bounds__(256) attn_kernel()
{
    __shared__ float Qs[64 * 64];
    __shared__ float KVs[64 * 64];
    __shared__ float Ps[64 * 64];

    const int qt = blockIdx.x;
    const int h  = blockIdx.y;
    const int b  = blockIdx.z;
    const int tid = threadIdx.x;
    const int tx = tid & 15;
    const int ty = tid >> 4;

    const size_t base = ((size_t)b * Hv + h) * Tv * HDv;
    const float* Qg = g_Q + base + (size_t)qt * 64 * 64;
    const float* Kg = g_K + base;
    const float* Vg = g_V + base;

    // Load Q tile (natural layout)
    #pragma unroll
    for (int u = 0; u < 4; u++) {
        int f = tid + u * 256;
        int r  = f >> 4;
        int d4 = (f & 15) << 2;
        *(float4*)&Qs[r * 64 + d4] = *(const float4*)(Qg + r * 64 + d4);
    }

    ull o2[4][2];
    float mrow[4], lrow[4];
    #pragma unroll
    for (int i = 0; i < 4; i++) {
        mrow[i] = NEG_INF;
        lrow[i] = 0.f;
        o2[i][0] = 0ull; o2[i][1] = 0ull;
    }

    const float scale = 0.125f;   // 1/sqrt(64)

    for (int kt = 0; kt <= qt; kt++) {
        __syncthreads();

        // Load K tile, swizzled
        #pragma unroll
        for (int u = 0; u < 4; u++) {
            int f = tid + u * 256;
            int c  = f >> 4;
            int d4 = (f & 15) << 2;
            *(float4*)&KVs[c * 64 + (d4 ^ (c & 60))] =
                *(const float4*)(Kg + (size_t)(kt * 64 + c) * 64 + d4);
        }
        __syncthreads();

        // S = Q @ K^T  — f32x2 paired over d (even/odd partial sums)
        ull s2[4][4];
        #pragma unroll
        for (int i = 0; i < 4; i++)
            #pragma unroll
            for (int j = 0; j < 4; j++) s2[i][j] = 0ull;

        #pragma unroll 4
        for (int d2 = 0; d2 < 32; d2++) {
            const int d = d2 * 2;
            ull qa2[4], kb2[4];
            #pragma unroll
            for (int i = 0; i < 4; i++)
                qa2[i] = *(const ull*)&Qs[(ty * 4 + i) * 64 + d];
            #pragma unroll
            for (int j = 0; j < 4; j++) {
                const int c = tx * 4 + j;
                kb2[j] = *(const ull*)&KVs[c * 64 + ((d & 60) ^ (c & 60)) + (d & 3)];
            }
            #pragma unroll
            for (int i = 0; i < 4; i++)
                #pragma unroll
                for (int j = 0; j < 4; j++)
                    fma2(s2[i][j], qa2[i], kb2[j]);
        }

        // Combine halves, scale, mask, online softmax
        float s[4][4];
        #pragma unroll
        for (int i = 0; i < 4; i++)
            #pragma unroll
            for (int j = 0; j < 4; j++) {
                float2 t = unpack2(s2[i][j]);
                s[i][j] = t.x + t.y;
            }

        #pragma unroll
        for (int i = 0; i < 4; i++) {
            float mx = NEG_INF;
            #pragma unroll
            for (int j = 0; j < 4; j++) {
                float v = s[i][j] * scale;
                if (kt == qt && (tx * 4 + j) > (ty * 4 + i)) v = NEG_INF;
                s[i][j] = v;
                mx = fmaxf(mx, v);
            }
            #pragma unroll
            for (int off = 8; off >= 1; off >>= 1)
                mx = fmaxf(mx, __shfl_xor_sync(0xffffffffu, mx, off));
            float mnew = fmaxf(mrow[i], mx);
            float corr = __expf(mrow[i] - mnew);
            float rs = 0.f;
            float p[4];
            #pragma unroll
            for (int j = 0; j < 4; j++) {
                p[j] = __expf(s[i][j] - mnew);
                rs += p[j];
            }
            #pragma unroll
            for (int off = 8; off >= 1; off >>= 1)
                rs += __shfl_xor_sync(0xffffffffu, rs, off);
            lrow[i] = lrow[i] * corr + rs;
            mrow[i] = mnew;
            ull c2 = pack2(corr, corr);
            o2[i][0] = mul2(o2[i][0], c2);
            o2[i][1] = mul2(o2[i][1], c2);
            // Store P row chunk (vectorized)
            *(float4*)&Ps[(ty * 4 + i) * 64 + tx * 4] = make_float4(p[0], p[1], p[2], p[3]);
        }
        __syncthreads();   // K reads done + P visible before V overwrite

        // Load V tile over K buffer, swizzled
        #pragma unroll
        for (int u = 0; u < 4; u++) {
            int f = tid + u * 256;
            int c  = f >> 4;
            int d4 = (f & 15) << 2;
            *(float4*)&KVs[c * 64 + (d4 ^ (c & 60))] =
                *(const float4*)(Vg + (size_t)(kt * 64 + c) * 64 + d4);
        }
        __syncthreads();

        // O += P @ V  — f32x2 paired over j
        #pragma unroll 8
        for (int c = 0; c < 64; c++) {
            float pa[4];
            #pragma unroll
            for (int i = 0; i < 4; i++) pa[i] = Ps[(ty * 4 + i) * 64 + c];
            ull vb2[2];
            #pragma unroll
            for (int jj = 0; jj < 2; jj++) {
                const int d = tx * 4 + 2 * jj;
                vb2[jj] = *(const ull*)&KVs[c * 64 + ((d & 60) ^ (c & 60)) + (d & 3)];
            }
            #pragma unroll
            for (int i = 0; i < 4; i++) {
                ull p2 = pack2(pa[i], pa[i]);
                fma2(o2[i][0], p2, vb2[0]);
                fma2(o2[i][1], p2, vb2[1]);
            }
        }
    }

    // Epilogue: normalize, write O in [B*T, C] layout (col = h*64 + tx*4..+3)
    #pragma unroll
    for (int i = 0; i < 4; i++) {
        float inv = 1.0f / lrow[i];
        int t = qt * 64 + ty * 4 + i;
        float2 u0 = unpack2(o2[i][0]);
        float2 u1 = unpack2(o2[i][1]);
        float4 ov = make_float4(u0.x * inv, u0.y * inv, u1.x * inv, u1.y * inv);
        *(float4*)&g_O[((size_t)b * Tv + t) * Cv + h * 64 + tx * 4] = ov;
    }
}

// ---------------------------------------------------------------------------
// Launch: QKV GEMM -> flash attention -> out-proj GEMM
// Inputs: x, mask(unused), W_qkv, b_qkv, W_proj, b_proj.
// ---------------------------------------------------------------------------
extern "C" void kernel_launch(void* const* d_in, const int* in_sizes, int n_in,
                              void* d_out, int out_size)
{
    const float* x      = (const float*)d_in[0];
    const float* W_qkv  = (const float*)d_in[2];
    const float* b_qkv  = (const float*)d_in[3];
    const float* W_proj = (const float*)d_in[4];
    const float* b_proj = (const float*)d_in[5];
    float* out = (float*)d_out;

    gemm_kernel<NQKV, true><<<dim3(NQKV / 128, Mv / 128), 256>>>(x, W_qkv, b_qkv, nullptr);
    attn_kernel<<<dim3(Tv / 64, Hv, Bv), 256>>>();
    gemm_kernel<Cv, false><<<dim3(Cv / 128, Mv / 128), 256>>>(nullptr, W_proj, b_proj, out);
}